// round 17
// baseline (speedup 1.0000x reference)
#include <cuda_runtime.h>
#include <cstddef>

#define BB 32
#define EE 256
#define SS 512
#define NVOCAB 10000
#define NBLK 128
#define NTHR 256
#define HSTR 260

// SMEM layout (floats)
#define OFF_WGF  0                       // 8 x HSTR : ln_g-folded w_ih[:,256:512] rows
#define OFF_WHH  (OFF_WGF + 8*HSTR)      // 8 x HSTR : w_hh rows
#define OFF_W2   (OFF_WHH + 8*HSTR)      // 2 x HSTR : w_outp[:,256:512] rows
#define OFF_S1   (OFF_W2 + 2*HSTR)
#define OFF_S2   (OFF_S1 + 8)
#define OFF_BIAS (OFF_S2 + 8)
#define OFF_BASE (OFF_BIAS + 8)          // 64 : ctx @ w_outp[:, :E]^T (b*2+cl)
#define OFF_F    (OFF_BASE + 64)         // 32 x HSTR : feed
#define OFF_H    (OFF_F + 32*HSTR)       // 32 x HSTR : h
#define SMEM_FLOATS 30720                // pad to 120KB so only 1 CTA/SM fits
#define SMEM_BYTES (SMEM_FLOATS * 4)

__device__ float g_y[SS*BB*EE];          // outs [t][b][k] (== next-step feed)
__device__ float g_h[BB*EE];
__device__ float g_ctx[BB*EE];           // enc_proj
__device__ float g_gx[(size_t)SS*BB*1024]; // precomputed x-half of gate dots [t*32+b][row]
__device__ float g_sumx[SS*BB];
__device__ float g_ssx[SS*BB];
__device__ unsigned g_flags[NBLK];       // distributed barrier flags (monotonic)

__device__ __forceinline__ float2 fma2(float2 a, float2 b, float2 c) {
    float2 d;
    asm("fma.rn.f32x2 %0, %1, %2, %3;"
        : "=l"(*reinterpret_cast<unsigned long long*>(&d))
        : "l"(*reinterpret_cast<const unsigned long long*>(&a)),
          "l"(*reinterpret_cast<const unsigned long long*>(&b)),
          "l"(*reinterpret_cast<const unsigned long long*>(&c)));
    return d;
}

__device__ __forceinline__ float sigm(float x) { return 1.0f / (1.0f + __expf(-x)); }

// Distributed sense-free barrier: per-CTA monotonic flag (release store),
// warp 0 acquire-polls all NBLK flags (4 per lane). No atomics anywhere.
__device__ __forceinline__ void gridbar(unsigned target) {
    __syncthreads();   // all block writes happen-before the release store below
    if (threadIdx.x == 0) {
        asm volatile("st.release.gpu.global.u32 [%0], %1;"
                     :: "l"(g_flags + blockIdx.x), "r"(target) : "memory");
    }
    if (threadIdx.x < 32) {
        const unsigned* p = g_flags + threadIdx.x * 4;
        for (;;) {
            unsigned v0, v1, v2, v3;
            asm volatile("ld.acquire.gpu.global.u32 %0, [%1];"    : "=r"(v0) : "l"(p)     : "memory");
            asm volatile("ld.acquire.gpu.global.u32 %0, [%1+4];"  : "=r"(v1) : "l"(p)     : "memory");
            asm volatile("ld.acquire.gpu.global.u32 %0, [%1+8];"  : "=r"(v2) : "l"(p)     : "memory");
            asm volatile("ld.acquire.gpu.global.u32 %0, [%1+12];" : "=r"(v3) : "l"(p)     : "memory");
            if (v0 >= target && v1 >= target && v2 >= target && v3 >= target) break;
        }
    }
    __syncthreads();   // acquire observation happens-before all block reads after
}

// ---------------- precompute: per-(b,t) LN partial sums of embedded token ----
__global__ void __launch_bounds__(256) stats_kernel(
    const int* __restrict__ tokens, const float* __restrict__ embed)
{
    int r = blockIdx.x * 8 + (threadIdx.x >> 5);   // r = t*32 + b
    int lane = threadIdx.x & 31;
    int b = r & 31, t = r >> 5;
    int tok = __ldg(&tokens[b * SS + t]);
    const float4* e4 = (const float4*)(embed + (size_t)tok * EE);
    float4 a = __ldg(e4 + lane * 2), c = __ldg(e4 + lane * 2 + 1);
    float s  = a.x + a.y + a.z + a.w + c.x + c.y + c.z + c.w;
    float ss = a.x*a.x + a.y*a.y + a.z*a.z + a.w*a.w
             + c.x*c.x + c.y*c.y + c.z*c.z + c.w*c.w;
    #pragma unroll
    for (int d = 16; d >= 1; d >>= 1) {
        s  += __shfl_xor_sync(~0u, s,  d);
        ss += __shfl_xor_sync(~0u, ss, d);
    }
    if (lane == 0) { g_sumx[r] = s; g_ssx[r] = ss; }
}

// ---------------- precompute: Gx[r][row] = (w_ih[row,:256]*ln_g) . embed[tok(r)]
__global__ void __launch_bounds__(256) gx_gemm(
    const int* __restrict__ tokens, const float* __restrict__ embed,
    const float* __restrict__ w_ih, const float* __restrict__ ln_g)
{
    __shared__ float sA[16][132];
    __shared__ float sB[16][132];
    const int tid = threadIdx.x;
    const int n0 = blockIdx.x * 128;   // gate row tile (0..1023)
    const int r0 = blockIdx.y * 128;   // (t*32+b) tile
    const int tx = tid & 15, ty = tid >> 4;
    const int m_a = tid >> 2, kq = tid & 3;

    float2 acc[8][4];
    #pragma unroll
    for (int i = 0; i < 8; i++)
        #pragma unroll
        for (int j = 0; j < 4; j++) acc[i][j] = make_float2(0.f, 0.f);

    for (int k0 = 0; k0 < 256; k0 += 16) {
        #pragma unroll
        for (int l = 0; l < 2; l++) {
            int m = m_a + l * 64;
            int r = r0 + m, b = r & 31, t = r >> 5;
            int tok = __ldg(&tokens[b * SS + t]);
            float4 v = __ldg((const float4*)(embed + (size_t)tok * EE + k0) + kq);
            sA[kq*4+0][m] = v.x; sA[kq*4+1][m] = v.y;
            sA[kq*4+2][m] = v.z; sA[kq*4+3][m] = v.w;
        }
        #pragma unroll
        for (int l = 0; l < 2; l++) {
            int n = m_a + l * 64;
            int gn = n0 + n;
            float4 v = __ldg((const float4*)(w_ih + (size_t)gn * 512 + k0) + kq);
            float4 g = __ldg((const float4*)(ln_g + k0) + kq);
            sB[kq*4+0][n] = v.x * g.x; sB[kq*4+1][n] = v.y * g.y;
            sB[kq*4+2][n] = v.z * g.z; sB[kq*4+3][n] = v.w * g.w;
        }
        __syncthreads();
        #pragma unroll
        for (int k = 0; k < 16; k++) {
            float4 a03 = *(const float4*)(&sA[k][ty * 8]);
            float4 a47 = *(const float4*)(&sA[k][ty * 8 + 4]);
            float4 b01 = *(const float4*)(&sB[k][tx * 8]);
            float4 b23 = *(const float4*)(&sB[k][tx * 8 + 4]);
            float  a[8]  = {a03.x, a03.y, a03.z, a03.w, a47.x, a47.y, a47.z, a47.w};
            float2 bv[4] = {make_float2(b01.x, b01.y), make_float2(b01.z, b01.w),
                            make_float2(b23.x, b23.y), make_float2(b23.z, b23.w)};
            #pragma unroll
            for (int i = 0; i < 8; i++)
                #pragma unroll
                for (int j = 0; j < 4; j++)
                    acc[i][j] = fma2(make_float2(a[i], a[i]), bv[j], acc[i][j]);
        }
        __syncthreads();
    }
    #pragma unroll
    for (int i = 0; i < 8; i++) {
        size_t r = (size_t)(r0 + ty * 8 + i);
        #pragma unroll
        for (int j = 0; j < 4; j++) {
            int col = n0 + tx * 8 + j * 2;
            g_gx[r * 1024 + col]     = acc[i][j].x;
            g_gx[r * 1024 + col + 1] = acc[i][j].y;
        }
    }
}

// ---------------- persistent recurrence ----------------
__global__ void __launch_bounds__(NTHR) decoder_persistent(
    const int*   __restrict__ tokens,
    const float* __restrict__ enc,
    const float* __restrict__ w_ih,
    const float* __restrict__ w_hh,
    const float* __restrict__ b_ih,
    const float* __restrict__ b_hh,
    const float* __restrict__ ln_g,
    const float* __restrict__ ln_b,
    const float* __restrict__ w_enc,
    const float* __restrict__ w_outp)
{
    extern __shared__ float sm[];
    const int tid  = threadIdx.x;
    const int bid  = blockIdx.x;
    const int c0   = 2 * bid;
    const int b    = tid >> 3;
    const int q    = tid & 7;
    const int cl   = q >> 2;
    const int gate = q & 3;
    const int lane = tid & 31;

    // barrier generation base (flags are uniform at every launch boundary)
    __shared__ unsigned s_base;
    if (tid == 0) {
        unsigned v;
        asm volatile("ld.global.cg.u32 %0, [%1];" : "=r"(v) : "l"(g_flags + bid));
        s_base = v;
    }

    // ---- weight slices into SMEM ----
    for (int idx = tid; idx < 8 * 256; idx += NTHR) {
        int qq = idx >> 8, m = idx & 255;
        int r = (qq & 3) * 256 + c0 + (qq >> 2);
        sm[OFF_WGF + qq * HSTR + m] = w_ih[(size_t)r * 512 + 256 + m] * ln_g[256 + m];
    }
    for (int idx = tid; idx < 8 * 256; idx += NTHR) {
        int qq = idx >> 8, m = idx & 255;
        int r = (qq & 3) * 256 + c0 + (qq >> 2);
        sm[OFF_WHH + qq * HSTR + m] = w_hh[(size_t)r * 256 + m];
    }
    for (int idx = tid; idx < 2 * 256; idx += NTHR) {
        int kl = idx >> 8, m = idx & 255;
        sm[OFF_W2 + kl * HSTR + m] = w_outp[(size_t)(c0 + kl) * 512 + 256 + m];
    }
    // s1/s2/bias: 32 lanes per row
    {
        int qq = tid >> 5, ln = tid & 31;
        int r = (qq & 3) * 256 + c0 + (qq >> 2);
        const float4* W4 = (const float4*)(w_ih + (size_t)r * 512 + ln * 16);
        const float4* G4 = (const float4*)(ln_g + ln * 16);
        const float4* B4 = (const float4*)(ln_b + ln * 16);
        float s1 = 0.f, s2 = 0.f;
        #pragma unroll
        for (int i = 0; i < 4; i++) {
            float4 w = __ldg(W4 + i), g = __ldg(G4 + i), bb2 = __ldg(B4 + i);
            s1 += w.x*g.x + w.y*g.y + w.z*g.z + w.w*g.w;
            s2 += w.x*bb2.x + w.y*bb2.y + w.z*bb2.z + w.w*bb2.w;
        }
        #pragma unroll
        for (int d = 16; d >= 1; d >>= 1) {
            s1 += __shfl_xor_sync(~0u, s1, d);
            s2 += __shfl_xor_sync(~0u, s2, d);
        }
        if (ln == 0) {
            sm[OFF_S1 + qq] = s1;
            sm[OFF_S2 + qq] = s2;
            sm[OFF_BIAS + qq] = b_ih[r] + b_hh[r];
        }
    }
    __syncthreads();
    unsigned tgt = s_base;

    // ---- prologue: enc_proj = enc @ w_enc^T ----
    {
        const float4* A4 = (const float4*)(enc + b * EE + gate * 64);
        const float4* W4 = (const float4*)(w_enc + (size_t)(c0 + cl) * EE + gate * 64);
        float acc = 0.0f;
        #pragma unroll
        for (int i = 0; i < 16; i++) {
            float4 a = __ldg(A4 + i), w = __ldg(W4 + i);
            acc += a.x*w.x + a.y*w.y + a.z*w.z + a.w*w.w;
        }
        acc += __shfl_xor_sync(~0u, acc, 1);
        acc += __shfl_xor_sync(~0u, acc, 2);
        if (gate == 0) __stcg(&g_ctx[b * EE + c0 + cl], acc);
    }
    gridbar(++tgt);
    // ---- prologue: base = ctx @ w_outp[:, :E]^T  (own columns -> smem) ----
    {
        const float4* A4 = (const float4*)(g_ctx + b * EE + gate * 64);
        const float4* W4 = (const float4*)(w_outp + (size_t)(c0 + cl) * 512 + gate * 64);
        float acc = 0.0f;
        #pragma unroll
        for (int i = 0; i < 16; i++) {
            float4 a = __ldcg(A4 + i);
            float4 w = __ldg(W4 + i);
            acc += a.x*w.x + a.y*w.y + a.z*w.z + a.w*w.w;
        }
        acc += __shfl_xor_sync(~0u, acc, 1);
        acc += __shfl_xor_sync(~0u, acc, 2);
        if (gate == 0) sm[OFF_BASE + b * 2 + cl] = acc;
    }
    // stage h0 = enc into SMEM
    for (int idx = tid; idx < 2048; idx += NTHR) {
        int sb = idx >> 6, j = idx & 63;
        ((float4*)(sm + OFF_H + sb * HSTR))[j] = __ldg(((const float4*)(enc + sb * EE)) + j);
    }
    __syncthreads();

    const float s1q   = sm[OFF_S1 + q];
    const float s2q   = sm[OFF_S2 + q];
    const float biasq = sm[OFF_BIAS + q];
    const float my_base = sm[OFF_BASE + b * 2 + cl];
    float c_reg = 0.0f;

    for (int t = 0; t < SS; t++) {
        // early scalar loads (hide latency under feed staging)
        const float gx  = __ldg(&g_gx[((size_t)t * 32 + b) * 1024 + (gate << 8) + c0 + cl]);
        const float sx  = __ldg(&g_sumx[t * 32 + b]);
        const float sxx = __ldg(&g_ssx[t * 32 + b]);

        // ---- stage feed (y_{t-1}) into SMEM ----
        for (int idx = tid; idx < 2048; idx += NTHR) {
            int sb = idx >> 6, j = idx & 63;
            float4 fv;
            if (t == 0) fv = make_float4(0.f, 0.f, 0.f, 0.f);
            else fv = __ldcg(((const float4*)(g_y + (size_t)(t - 1) * BB * EE + sb * EE)) + j);
            ((float4*)(sm + OFF_F + sb * HSTR))[j] = fv;
        }
        __syncthreads();

        // ---- LN stats (feed part; x part precomputed) ----
        float s = 0.0f, ss = 0.0f;
        {
            const float4* f4 = (const float4*)(sm + OFF_F + b * HSTR);
            #pragma unroll
            for (int i = 0; i < 8; i++) {
                float4 v = f4[q * 8 + i];
                s  += v.x + v.y + v.z + v.w;
                ss += v.x*v.x + v.y*v.y + v.z*v.z + v.w*v.w;
            }
            s  += __shfl_xor_sync(~0u, s, 1);  ss += __shfl_xor_sync(~0u, ss, 1);
            s  += __shfl_xor_sync(~0u, s, 2);  ss += __shfl_xor_sync(~0u, ss, 2);
            s  += __shfl_xor_sync(~0u, s, 4);  ss += __shfl_xor_sync(~0u, ss, 4);
        }
        const float mu   = (sx + s) * (1.0f / 512.0f);
        const float var  = (sxx + ss) * (1.0f / 512.0f) - mu * mu;
        const float rstd = rsqrtf(var + 1e-5f);

        // ---- gate pre-activation ----
        float2 a0 = make_float2(0.f, 0.f), a1 = make_float2(0.f, 0.f);
        {
            const float4* W4 = (const float4*)(sm + OFF_WGF + q * HSTR);
            const float4* V4 = (const float4*)(sm + OFF_F + b * HSTR);
            #pragma unroll 8
            for (int i = 0; i < 64; i++) {
                float4 w = W4[i], v = V4[i];
                a0 = fma2(make_float2(w.x, w.y), make_float2(v.x, v.y), a0);
                a1 = fma2(make_float2(w.z, w.w), make_float2(v.z, v.w), a1);
            }
        }
        float2 h0 = make_float2(0.f, 0.f), h1 = make_float2(0.f, 0.f);
        {
            const float4* W4 = (const float4*)(sm + OFF_WHH + q * HSTR);
            const float4* H4 = (const float4*)(sm + OFF_H + b * HSTR);
            #pragma unroll 8
            for (int i = 0; i < 64; i++) {
                float4 w = W4[i], v = H4[i];
                h0 = fma2(make_float2(w.x, w.y), make_float2(v.x, v.y), h0);
                h1 = fma2(make_float2(w.z, w.w), make_float2(v.z, v.w), h1);
            }
        }
        const float accF = a0.x + a0.y + a1.x + a1.y;
        const float accH = h0.x + h0.y + h1.x + h1.y;
        const float gp = rstd * (gx + accF - mu * s1q) + s2q + accH + biasq;

        // ---- LSTM cell update ----
        const float gi = __shfl_sync(~0u, gp, lane & ~3);
        const float gf = __shfl_sync(~0u, gp, (lane & ~3) | 1);
        const float gg = __shfl_sync(~0u, gp, (lane & ~3) | 2);
        const float go = __shfl_sync(~0u, gp, (lane & ~3) | 3);
        if (gate == 0) {
            float cn = sigm(gf) * c_reg + sigm(gi) * tanhf(gg);
            c_reg = cn;
            float hn = sigm(go) * tanhf(cn);
            __stcg(&g_h[b * EE + c0 + cl], hn);
        }
        gridbar(++tgt);

        // ---- stage h_t into SMEM (used by phase B now and phase A next step) ----
        for (int idx = tid; idx < 2048; idx += NTHR) {
            int sb = idx >> 6, j = idx & 63;
            ((float4*)(sm + OFF_H + sb * HSTR))[j] = __ldcg(((const float4*)(g_h + sb * EE)) + j);
        }
        __syncthreads();

        // ---- phase B: y = tanh(base + h @ w_outp[:,E:]^T) ----
        {
            const float4* W4 = (const float4*)(sm + OFF_W2 + cl * HSTR);
            const float4* H4 = (const float4*)(sm + OFF_H + b * HSTR);
            float2 p0 = make_float2(0.f, 0.f), p1 = make_float2(0.f, 0.f);
            #pragma unroll
            for (int i = 0; i < 16; i++) {
                float4 w  = W4[gate * 16 + i];
                float4 hh = H4[gate * 16 + i];
                p0 = fma2(make_float2(w.x, w.y), make_float2(hh.x, hh.y), p0);
                p1 = fma2(make_float2(w.z, w.w), make_float2(hh.z, hh.w), p1);
            }
            float acc = p0.x + p0.y + p1.x + p1.y;
            acc += __shfl_xor_sync(~0u, acc, 1);
            acc += __shfl_xor_sync(~0u, acc, 2);
            if (gate == 0) {
                float o = tanhf(my_base + acc);
                __stcg(&g_y[(size_t)t * BB * EE + b * EE + c0 + cl], o);
            }
        }
        gridbar(++tgt);
    }
}

// ---------------- logits GEMM (unchanged) ----------------
__global__ void __launch_bounds__(256) fc_gemm(
    const float* __restrict__ wfc, const float* __restrict__ bfc,
    float* __restrict__ out)
{
    __shared__ float sA[16][132];
    __shared__ float sB[16][132];
    const int tid = threadIdx.x;
    const int n0  = blockIdx.x * 128;
    const int r0  = blockIdx.y * 128;
    const int bb  = r0 >> 9;
    const int t0  = r0 & 511;
    const int tx  = tid & 15, ty = tid >> 4;
    const int m_a = tid >> 2;
    const int kq  = tid & 3;

    float2 acc[8][4];
    #pragma unroll
    for (int i = 0; i < 8; i++)
        #pragma unroll
        for (int j = 0; j < 4; j++) acc[i][j] = make_float2(0.f, 0.f);

    for (int k0 = 0; k0 < 256; k0 += 16) {
        #pragma unroll
        for (int l = 0; l < 2; l++) {
            int m = m_a + l * 64;
            float4 v = *(const float4*)(g_y + (size_t)(t0 + m) * (BB * EE) + bb * EE + k0 + kq * 4);
            sA[kq*4+0][m] = v.x; sA[kq*4+1][m] = v.y;
            sA[kq*4+2][m] = v.z; sA[kq*4+3][m] = v.w;
        }
        #pragma unroll
        for (int l = 0; l < 2; l++) {
            int n = m_a + l * 64;
            int gn = n0 + n;
            float4 v = make_float4(0.f, 0.f, 0.f, 0.f);
            if (gn < NVOCAB) v = *(const float4*)(wfc + (size_t)gn * EE + k0 + kq * 4);
            sB[kq*4+0][n] = v.x; sB[kq*4+1][n] = v.y;
            sB[kq*4+2][n] = v.z; sB[kq*4+3][n] = v.w;
        }
        __syncthreads();
        #pragma unroll
        for (int k = 0; k < 16; k++) {
            float4 a03 = *(const float4*)(&sA[k][ty * 8]);
            float4 a47 = *(const float4*)(&sA[k][ty * 8 + 4]);
            float4 b01 = *(const float4*)(&sB[k][tx * 8]);
            float4 b23 = *(const float4*)(&sB[k][tx * 8 + 4]);
            float  a[8]  = {a03.x, a03.y, a03.z, a03.w, a47.x, a47.y, a47.z, a47.w};
            float2 bv[4] = {make_float2(b01.x, b01.y), make_float2(b01.z, b01.w),
                            make_float2(b23.x, b23.y), make_float2(b23.z, b23.w)};
            #pragma unroll
            for (int i = 0; i < 8; i++)
                #pragma unroll
                for (int j = 0; j < 4; j++)
                    acc[i][j] = fma2(make_float2(a[i], a[i]), bv[j], acc[i][j]);
        }
        __syncthreads();
    }

    #pragma unroll
    for (int i = 0; i < 8; i++) {
        size_t r = (size_t)(r0 + ty * 8 + i);
        #pragma unroll
        for (int j = 0; j < 4; j++) {
            int n = n0 + tx * 8 + j * 2;
            if (n < NVOCAB)     out[r * NVOCAB + n]     = acc[i][j].x + bfc[n];
            if (n + 1 < NVOCAB) out[r * NVOCAB + n + 1] = acc[i][j].y + bfc[n + 1];
        }
    }
}

extern "C" void kernel_launch(void* const* d_in, const int* in_sizes, int n_in,
                              void* d_out, int out_size) {
    (void)in_sizes; (void)n_in; (void)out_size;
    const int*   tokens = (const int*)  d_in[0];
    const float* enc    = (const float*)d_in[1];
    const float* embed  = (const float*)d_in[2];
    const float* w_ih   = (const float*)d_in[3];
    const float* w_hh   = (const float*)d_in[4];
    const float* b_ih   = (const float*)d_in[5];
    const float* b_hh   = (const float*)d_in[6];
    const float* ln_g   = (const float*)d_in[7];
    const float* ln_b   = (const float*)d_in[8];
    // d_in[9] = w_inp : dead (softmax over srclen=1 collapses attention)
    const float* w_enc  = (const float*)d_in[10];
    const float* w_outp = (const float*)d_in[11];
    const float* w_fc   = (const float*)d_in[12];
    const float* b_fc   = (const float*)d_in[13];
    float* out = (float*)d_out;

    cudaFuncSetAttribute(decoder_persistent,
                         cudaFuncAttributeMaxDynamicSharedMemorySize, SMEM_BYTES);

    stats_kernel<<<(SS * BB) / 8, 256>>>(tokens, embed);
    gx_gemm<<<dim3(8, (SS * BB) / 128), 256>>>(tokens, embed, w_ih, ln_g);
    decoder_persistent<<<NBLK, NTHR, SMEM_BYTES>>>(
        tokens, enc, w_ih, w_hh, b_ih, b_hh, ln_g, ln_b, w_enc, w_outp);
    dim3 grid((NVOCAB + 127) / 128, (BB * SS) / 128);
    fc_gemm<<<grid, 256>>>(w_fc, b_fc, out);
}